// round 6
// baseline (speedup 1.0000x reference)
#include <cuda_runtime.h>
#include <math_constants.h>

// ---------------------------------------------------------------------------
// Gaussian splatting forward, N=2048 -> 128x128x3. Single fused kernel:
//   preprocess -> gridbar -> rank-sort+scatter -> gridbar -> 8x8-tile raster.
// 256 blocks x 64 threads (all co-resident -> spin barrier safe).
// ---------------------------------------------------------------------------

#define NG      2048
#define IMG     128
#define TILE    8
#define TILES_X 16
#define NBLK    256
#define TPB     64
#define TAU     32.0f    // skip where power*log2e < -TAU

// Device scratch
__device__ float4 g_u0[NG];      // {u, v, A2, B2}
__device__ float4 g_u1[NG];      // {C2, lop, r, g}
__device__ float  g_ub[NG];      // b
__device__ float2 g_ubb[NG];     // bbox half extents
__device__ float  g_key[NG];
__device__ float4 g_s0[NG];      // sorted
__device__ float4 g_s1[NG];
__device__ float  g_sb[NG];
__device__ float2 g_sbb[NG];
__device__ unsigned g_bar;       // monotone grid-barrier counter (zero-init)

__device__ __forceinline__ float frcp(float x)   { float r; asm("rcp.approx.ftz.f32 %0,%1;"  :"=f"(r):"f"(x)); return r; }
__device__ __forceinline__ float frsqrt(float x) { float r; asm("rsqrt.approx.ftz.f32 %0,%1;":"=f"(r):"f"(x)); return r; }
__device__ __forceinline__ float fex2(float x)   { float r; asm("ex2.approx.ftz.f32 %0,%1;"  :"=f"(r):"f"(x)); return r; }
__device__ __forceinline__ float flg2(float x)   { float r; asm("lg2.approx.ftz.f32 %0,%1;"  :"=f"(r):"f"(x)); return r; }

// Monotone-counter grid barrier; arrivals for instance p are tickets
// [NBLK*p, NBLK*(p+1)), so target = (ticket/NBLK + 1)*NBLK. Replay-safe.
__device__ __forceinline__ void grid_barrier() {
    __syncthreads();
    __threadfence();
    if (threadIdx.x == 0) {
        unsigned tk = atomicAdd(&g_bar, 1u);
        unsigned target = ((tk >> 8) + 1u) << 8;      // NBLK = 256
        while (*(volatile unsigned*)&g_bar < target) { }
    }
    __syncthreads();
    __threadfence();
}

__device__ __forceinline__ void quat_to_rot(float w, float x, float y, float z, float* R) {
    float inv = frsqrt(w*w + x*x + y*y + z*z);
    w *= inv; x *= inv; y *= inv; z *= inv;
    R[0] = 1.0f - 2.0f*(y*y + z*z);
    R[1] = 2.0f*(x*y - w*z);
    R[2] = 2.0f*(x*z + w*y);
    R[3] = 2.0f*(x*y + w*z);
    R[4] = 1.0f - 2.0f*(x*x + z*z);
    R[5] = 2.0f*(y*z - w*x);
    R[6] = 2.0f*(x*z + w*x);   // placeholder, fixed below
    R[7] = 2.0f*(y*z + w*x);
    R[8] = 1.0f - 2.0f*(x*x + y*y);
    R[6] = 2.0f*(x*z - w*y);   // correct value (avoid typo risk)
}

// Shared memory union (phases separated by barriers):
//  Phase 2: keys 2048 f32 [0,8192) ; part 64 i32 [8192,8448)
//  Phase 3: list 2048 u16 [0,4096) ; cnt 64 i32 [4096,4352) ;
//           sc0 64 f4 [4352,5376) ; sc1 64 f4 [5376,6400) ; scb 64 f [6400,6656)
#define SMEM_BYTES 8448

__global__ void __launch_bounds__(TPB) k_fused(
        const float* __restrict__ pos,  const float* __restrict__ rgb,
        const float* __restrict__ opa,  const float* __restrict__ quat,
        const float* __restrict__ scale,const float* __restrict__ wq,
        const float* __restrict__ wt,   float* __restrict__ out) {
    __shared__ __align__(16) unsigned char sraw[SMEM_BYTES];

    const int t = threadIdx.x;
    const int b = blockIdx.x;
    const int lane = t & 31;
    const int wid  = t >> 5;

    // ===================== Phase 1: preprocess (8 gaussians/block) ==========
    if (t < 8) {
        int i = b * 8 + t;

        float R[9];
        quat_to_rot(wq[0], wq[1], wq[2], wq[3], R);

        float px = pos[3*i], py = pos[3*i+1], pz = pos[3*i+2];
        float x = R[0]*px + R[1]*py + R[2]*pz + wt[0];
        float y = R[3]*px + R[4]*py + R[5]*pz + wt[1];
        float z = R[6]*px + R[7]*py + R[8]*pz + wt[2];
        float d2 = x*x + y*y + z*z;

        bool mask = z > 1.1f;
        float zs = mask ? z : 1.0f;
        float iz = frcp(zs);
        float u = x * iz;
        float v = y * iz;
        mask = mask && (fabsf(u) < 0.64f) && (fabsf(v) < 0.64f);

        float iz2 = iz * iz;
        float J02 = -x * iz2, J12 = -y * iz2;
        float JW0[3], JW1[3];
        #pragma unroll
        for (int k = 0; k < 3; k++) {
            JW0[k] = iz * R[k]   + J02 * R[6+k];
            JW1[k] = iz * R[3+k] + J12 * R[6+k];
        }

        float Rg[9];
        quat_to_rot(quat[4*i], quat[4*i+1], quat[4*i+2], quat[4*i+3], Rg);
        float s0 = scale[3*i], s1 = scale[3*i+1], s2 = scale[3*i+2];
        float RS[9];
        #pragma unroll
        for (int r = 0; r < 3; r++) {
            RS[3*r+0] = Rg[3*r+0] * s0;
            RS[3*r+1] = Rg[3*r+1] * s1;
            RS[3*r+2] = Rg[3*r+2] * s2;
        }
        float c00 = RS[0]*RS[0] + RS[1]*RS[1] + RS[2]*RS[2];
        float c01 = RS[0]*RS[3] + RS[1]*RS[4] + RS[2]*RS[5];
        float c02 = RS[0]*RS[6] + RS[1]*RS[7] + RS[2]*RS[8];
        float c11 = RS[3]*RS[3] + RS[4]*RS[4] + RS[5]*RS[5];
        float c12 = RS[3]*RS[6] + RS[4]*RS[7] + RS[5]*RS[8];
        float c22 = RS[6]*RS[6] + RS[7]*RS[7] + RS[8]*RS[8];

        float M0x = JW0[0]*c00 + JW0[1]*c01 + JW0[2]*c02;
        float M0y = JW0[0]*c01 + JW0[1]*c11 + JW0[2]*c12;
        float M0z = JW0[0]*c02 + JW0[1]*c12 + JW0[2]*c22;
        float M1x = JW1[0]*c00 + JW1[1]*c01 + JW1[2]*c02;
        float M1y = JW1[0]*c01 + JW1[1]*c11 + JW1[2]*c12;
        float M1z = JW1[0]*c02 + JW1[1]*c12 + JW1[2]*c22;

        float a = M0x*JW0[0] + M0y*JW0[1] + M0z*JW0[2] + 1e-6f;
        float bq= M0x*JW1[0] + M0y*JW1[1] + M0z*JW1[2];
        float c = M1x*JW1[0] + M1y*JW1[1] + M1z*JW1[2] + 1e-6f;

        float det = fmaxf(a*c - bq*bq, 1e-12f);
        float invdet = frcp(det);
        float Ap = c  * invdet;
        float Bp = bq * invdet;
        float Cp = a  * invdet;

        const float L2E = 1.4426950408889634f;
        float A2 = -0.5f * Ap * L2E;
        float B2 =         Bp * L2E;
        float C2 = -0.5f * Cp * L2E;

        // Conservative bbox of {quadratic <= 2t}: |dx| <= sqrt(2t*Cp/detM)
        float detM = det * invdet * invdet;
        float twot = 2.0f * (TAU / L2E);
        float bx, by;
        if (detM > 0.0f && isfinite(detM)) {
            float inv_dm = 1.02f * frcp(detM);
            bx = sqrtf(fmaxf(twot * Cp * inv_dm, 0.0f));
            by = sqrtf(fmaxf(twot * Ap * inv_dm, 0.0f));
            if (!isfinite(bx) || !isfinite(by)) { bx = 1e9f; by = 1e9f; }
        } else {
            bx = 1e9f; by = 1e9f;
        }
        if (!mask) { bx = -1e9f; by = -1e9f; }    // always culled (alpha=0 anyway)

        float op = mask ? opa[i] : 0.0f;
        float lop = flg2(op);                     // -inf if masked (never listed)

        g_u0[i]  = make_float4(u, v, A2, B2);
        g_u1[i]  = make_float4(C2, lop, rgb[3*i], rgb[3*i+1]);
        g_ub[i]  = rgb[3*i+2];
        g_ubb[i] = make_float2(bx, by);
        g_key[i] = mask ? d2 : CUDART_INF_F;
    }

    grid_barrier();

    // ===================== Phase 2: stable rank sort ========================
    {
        float* s_keys = (float*)sraw;             // 2048
        int*   s_part = (int*)(sraw + 8192);      // 8 gaussians x 8 segs

        #pragma unroll
        for (int c = 0; c < 8; c++) {
            float4 k4 = ((const float4*)g_key)[c*64 + t];
            ((float4*)s_keys)[c*64 + t] = k4;
        }
        __syncthreads();

        int gi  = t >> 3;            // 0..7 gaussian within block
        int seg = t & 7;             // 0..7 key segment (256 keys)
        int i = b * 8 + gi;
        float ki = s_keys[i];
        int part = 0;
        const float4* k4 = (const float4*)s_keys + seg * 64;
        #pragma unroll 8
        for (int j4 = 0; j4 < 64; j4++) {
            float4 kk = k4[j4];
            int j = seg*256 + j4*4;
            part += (kk.x < ki) || (kk.x == ki && (j+0) < i);
            part += (kk.y < ki) || (kk.y == ki && (j+1) < i);
            part += (kk.z < ki) || (kk.z == ki && (j+2) < i);
            part += (kk.w < ki) || (kk.w == ki && (j+3) < i);
        }
        s_part[gi*8 + seg] = part;
        __syncthreads();

        if (t < 8) {
            int i2 = b * 8 + t;
            int rank = 0;
            #pragma unroll
            for (int s = 0; s < 8; s++) rank += s_part[t*8 + s];
            g_s0[rank]  = g_u0[i2];
            g_s1[rank]  = g_u1[i2];
            g_sb[rank]  = g_ub[i2];
            g_sbb[rank] = g_ubb[i2];
        }
    }

    grid_barrier();

    // ===================== Phase 3: 8x8-tile raster =========================
    {
        unsigned short* s_list = (unsigned short*)sraw;      // 2048
        int*    s_cnt = (int*)(sraw + 4096);                 // 32 chunks x 2 warps
        float4* sc0   = (float4*)(sraw + 4352);              // 64
        float4* sc1   = (float4*)(sraw + 5376);              // 64
        float*  scb   = (float*)(sraw + 6400);               // 64

        int tx = b & (TILES_X - 1);
        int ty = b >> 4;

        float ulo = ((float)(tx * TILE) + 0.5f - 64.0f) * 0.01f;
        float uhi = ulo + 7.0f * 0.01f;
        float vlo = ((float)(ty * TILE) + 0.5f - 64.0f) * 0.01f;
        float vhi = vlo + 7.0f * 0.01f;

        // --- Phase A pass 1: keep bits + per-(chunk,warp) counts ---
        unsigned keepbits = 0;
        #pragma unroll 4
        for (int c = 0; c < 32; c++) {
            int g = c * 64 + t;
            float4 p0 = g_s0[g];
            float2 bb = g_sbb[g];
            bool keep = (p0.x + bb.x >= ulo) && (p0.x - bb.x <= uhi) &&
                        (p0.y + bb.y >= vlo) && (p0.y - bb.y <= vhi);
            unsigned m = __ballot_sync(0xffffffffu, keep);
            keepbits |= ((unsigned)keep) << c;
            if (lane == 0) s_cnt[c*2 + wid] = __popc(m);
        }
        __syncthreads();

        // --- Phase A pass 2: ordered scatter via running prefix ---
        unsigned lmask = (1u << lane) - 1u;
        int run = 0;
        #pragma unroll 4
        for (int c = 0; c < 32; c++) {
            unsigned m = __ballot_sync(0xffffffffu, (keepbits >> c) & 1u);
            int c0 = s_cnt[c*2], c1 = s_cnt[c*2 + 1];
            if ((keepbits >> c) & 1u) {
                int off = run + (wid ? c0 : 0) + __popc(m & lmask);
                s_list[off] = (unsigned short)(c * 64 + t);
            }
            run += c0 + c1;
        }
        int L = run;
        __syncthreads();

        // --- Phase B: composite in depth order, staged 64-at-a-time ---
        int pi = ty * TILE + (t >> 3);
        int pj = tx * TILE + (t & 7);
        float pu = ((float)pj + 0.5f - 64.0f) * 0.01f;
        float pv = ((float)pi + 0.5f - 64.0f) * 0.01f;

        float T = 1.0f, cr = 0.0f, cg = 0.0f, cb = 0.0f;

        for (int base = 0; base < L; base += 64) {
            int n = min(64, L - base);
            if (t < n) {
                int g = s_list[base + t];
                sc0[t] = g_s0[g];
                sc1[t] = g_s1[g];
                scb[t] = g_sb[g];
            }
            __syncthreads();

            #pragma unroll 4
            for (int j = 0; j < n; j++) {
                float4 p0 = sc0[j];          // u, v, A2, B2
                float4 p1 = sc1[j];          // C2, lop, r, g
                float  bb = scb[j];
                float dx = pu - p0.x;
                float dy = pv - p0.y;
                float t4 = fmaf(p1.x, dy*dy, p1.y);                   // C2 dy^2 + lop
                float pw = fmaf(dx, fmaf(p0.z, dx, p0.w*dy), t4);     // + A2 dx^2 + B2 dx dy
                pw = fminf(pw, p1.y);        // == min(raw,0)+lop
                float alpha = fex2(pw);      // opa*exp(min(power,0)); <=0.9 so no clamp
                float w = T * alpha;
                cr = fmaf(w, p1.z, cr);
                cg = fmaf(w, p1.w, cg);
                cb = fmaf(w, bb, cb);
                T -= w;
            }
            if (__syncthreads_and(T < 1e-7f)) break;   // also the barrier for re-staging
        }

        int pix = pi * IMG + pj;
        out[3*pix + 0] = cr;
        out[3*pix + 1] = cg;
        out[3*pix + 2] = cb;
    }
}

// ---------------------------------------------------------------------------
extern "C" void kernel_launch(void* const* d_in, const int* in_sizes, int n_in,
                              void* d_out, int out_size) {
    const float* pos   = (const float*)d_in[0];
    const float* rgb   = (const float*)d_in[1];
    const float* opa   = (const float*)d_in[2];
    const float* quat  = (const float*)d_in[3];
    const float* scale = (const float*)d_in[4];
    const float* wq    = (const float*)d_in[5];
    const float* wt    = (const float*)d_in[6];
    float* out = (float*)d_out;

    k_fused<<<NBLK, TPB>>>(pos, rgb, opa, quat, scale, wq, wt, out);
}

// round 11
// speedup vs baseline: 1.0851x; 1.0851x over previous
#include <cuda_runtime.h>
#include <math_constants.h>

// ---------------------------------------------------------------------------
// Gaussian splatting forward, N=2048 -> 128x128x3. Single fused kernel:
//   preprocess -> gridbar -> rank-sort+scatter -> gridbar -> 8x8-tile raster.
// 256 blocks x 64 threads (all co-resident -> spin barrier safe).
// ---------------------------------------------------------------------------

#define NG      2048
#define IMG     128
#define TILE    8
#define TILES_X 16
#define NBLK    256
#define TPB     64
#define TAU     32.0f    // skip where power*log2e < -TAU

// Device scratch
__device__ float4 g_u0[NG];      // {u, v, A2, B2}
__device__ float4 g_u1[NG];      // {C2, lop, r, g}
__device__ float  g_ub[NG];      // b
__device__ float2 g_ubb[NG];     // bbox half extents
__device__ float  g_key[NG];
__device__ float4 g_s0[NG];      // sorted
__device__ float4 g_s1[NG];
__device__ float  g_sb[NG];
__device__ float2 g_sbb[NG];
__device__ unsigned g_bar;       // monotone grid-barrier counter (zero-init)

__device__ __forceinline__ float frcp(float x)   { float r; asm("rcp.approx.ftz.f32 %0,%1;"  :"=f"(r):"f"(x)); return r; }
__device__ __forceinline__ float frsqrt(float x) { float r; asm("rsqrt.approx.ftz.f32 %0,%1;":"=f"(r):"f"(x)); return r; }
__device__ __forceinline__ float fex2(float x)   { float r; asm("ex2.approx.ftz.f32 %0,%1;"  :"=f"(r):"f"(x)); return r; }
__device__ __forceinline__ float flg2(float x)   { float r; asm("lg2.approx.ftz.f32 %0,%1;"  :"=f"(r):"f"(x)); return r; }

// Monotone-counter grid barrier; arrivals for instance p are tickets
// [NBLK*p, NBLK*(p+1)), so target = (ticket/NBLK + 1)*NBLK. Replay-safe.
__device__ __forceinline__ void grid_barrier() {
    __syncthreads();
    __threadfence();
    if (threadIdx.x == 0) {
        unsigned tk = atomicAdd(&g_bar, 1u);
        unsigned target = ((tk >> 8) + 1u) << 8;      // NBLK = 256
        while (*(volatile unsigned*)&g_bar < target) { }
    }
    __syncthreads();
    __threadfence();
}

__device__ __forceinline__ void quat_to_rot(float w, float x, float y, float z, float* R) {
    float inv = frsqrt(w*w + x*x + y*y + z*z);
    w *= inv; x *= inv; y *= inv; z *= inv;
    R[0] = 1.0f - 2.0f*(y*y + z*z);
    R[1] = 2.0f*(x*y - w*z);
    R[2] = 2.0f*(x*z + w*y);
    R[3] = 2.0f*(x*y + w*z);
    R[4] = 1.0f - 2.0f*(x*x + z*z);
    R[5] = 2.0f*(y*z - w*x);
    R[6] = 2.0f*(x*z + w*x);   // placeholder, fixed below
    R[7] = 2.0f*(y*z + w*x);
    R[8] = 1.0f - 2.0f*(x*x + y*y);
    R[6] = 2.0f*(x*z - w*y);   // correct value (avoid typo risk)
}

// Shared memory union (phases separated by barriers):
//  Phase 2: keys 2048 f32 [0,8192) ; part 64 i32 [8192,8448)
//  Phase 3: list 2048 u16 [0,4096) ; cnt 64 i32 [4096,4352) ;
//           sc0 64 f4 [4352,5376) ; sc1 64 f4 [5376,6400) ; scb 64 f [6400,6656)
#define SMEM_BYTES 8448

__global__ void __launch_bounds__(TPB) k_fused(
        const float* __restrict__ pos,  const float* __restrict__ rgb,
        const float* __restrict__ opa,  const float* __restrict__ quat,
        const float* __restrict__ scale,const float* __restrict__ wq,
        const float* __restrict__ wt,   float* __restrict__ out) {
    __shared__ __align__(16) unsigned char sraw[SMEM_BYTES];

    const int t = threadIdx.x;
    const int b = blockIdx.x;
    const int lane = t & 31;
    const int wid  = t >> 5;

    // ===================== Phase 1: preprocess (8 gaussians/block) ==========
    if (t < 8) {
        int i = b * 8 + t;

        float R[9];
        quat_to_rot(wq[0], wq[1], wq[2], wq[3], R);

        float px = pos[3*i], py = pos[3*i+1], pz = pos[3*i+2];
        float x = R[0]*px + R[1]*py + R[2]*pz + wt[0];
        float y = R[3]*px + R[4]*py + R[5]*pz + wt[1];
        float z = R[6]*px + R[7]*py + R[8]*pz + wt[2];
        float d2 = x*x + y*y + z*z;

        bool mask = z > 1.1f;
        float zs = mask ? z : 1.0f;
        float iz = frcp(zs);
        float u = x * iz;
        float v = y * iz;
        mask = mask && (fabsf(u) < 0.64f) && (fabsf(v) < 0.64f);

        float iz2 = iz * iz;
        float J02 = -x * iz2, J12 = -y * iz2;
        float JW0[3], JW1[3];
        #pragma unroll
        for (int k = 0; k < 3; k++) {
            JW0[k] = iz * R[k]   + J02 * R[6+k];
            JW1[k] = iz * R[3+k] + J12 * R[6+k];
        }

        float Rg[9];
        quat_to_rot(quat[4*i], quat[4*i+1], quat[4*i+2], quat[4*i+3], Rg);
        float s0 = scale[3*i], s1 = scale[3*i+1], s2 = scale[3*i+2];
        float RS[9];
        #pragma unroll
        for (int r = 0; r < 3; r++) {
            RS[3*r+0] = Rg[3*r+0] * s0;
            RS[3*r+1] = Rg[3*r+1] * s1;
            RS[3*r+2] = Rg[3*r+2] * s2;
        }
        float c00 = RS[0]*RS[0] + RS[1]*RS[1] + RS[2]*RS[2];
        float c01 = RS[0]*RS[3] + RS[1]*RS[4] + RS[2]*RS[5];
        float c02 = RS[0]*RS[6] + RS[1]*RS[7] + RS[2]*RS[8];
        float c11 = RS[3]*RS[3] + RS[4]*RS[4] + RS[5]*RS[5];
        float c12 = RS[3]*RS[6] + RS[4]*RS[7] + RS[5]*RS[8];
        float c22 = RS[6]*RS[6] + RS[7]*RS[7] + RS[8]*RS[8];

        float M0x = JW0[0]*c00 + JW0[1]*c01 + JW0[2]*c02;
        float M0y = JW0[0]*c01 + JW0[1]*c11 + JW0[2]*c12;
        float M0z = JW0[0]*c02 + JW0[1]*c12 + JW0[2]*c22;
        float M1x = JW1[0]*c00 + JW1[1]*c01 + JW1[2]*c02;
        float M1y = JW1[0]*c01 + JW1[1]*c11 + JW1[2]*c12;
        float M1z = JW1[0]*c02 + JW1[1]*c12 + JW1[2]*c22;

        float a = M0x*JW0[0] + M0y*JW0[1] + M0z*JW0[2] + 1e-6f;
        float bq= M0x*JW1[0] + M0y*JW1[1] + M0z*JW1[2];
        float c = M1x*JW1[0] + M1y*JW1[1] + M1z*JW1[2] + 1e-6f;

        float det = fmaxf(a*c - bq*bq, 1e-12f);
        float invdet = frcp(det);
        float Ap = c  * invdet;
        float Bp = bq * invdet;
        float Cp = a  * invdet;

        const float L2E = 1.4426950408889634f;
        float A2 = -0.5f * Ap * L2E;
        float B2 =         Bp * L2E;
        float C2 = -0.5f * Cp * L2E;

        // Conservative bbox of {quadratic <= 2t}: |dx| <= sqrt(2t*Cp/detM)
        float detM = det * invdet * invdet;
        float twot = 2.0f * (TAU / L2E);
        float bx, by;
        if (detM > 0.0f && isfinite(detM)) {
            float inv_dm = 1.02f * frcp(detM);
            bx = sqrtf(fmaxf(twot * Cp * inv_dm, 0.0f));
            by = sqrtf(fmaxf(twot * Ap * inv_dm, 0.0f));
            if (!isfinite(bx) || !isfinite(by)) { bx = 1e9f; by = 1e9f; }
        } else {
            bx = 1e9f; by = 1e9f;
        }
        if (!mask) { bx = -1e9f; by = -1e9f; }    // always culled (alpha=0 anyway)

        float op = mask ? opa[i] : 0.0f;
        float lop = flg2(op);                     // -inf if masked (never listed)

        g_u0[i]  = make_float4(u, v, A2, B2);
        g_u1[i]  = make_float4(C2, lop, rgb[3*i], rgb[3*i+1]);
        g_ub[i]  = rgb[3*i+2];
        g_ubb[i] = make_float2(bx, by);
        g_key[i] = mask ? d2 : CUDART_INF_F;
    }

    grid_barrier();

    // ===================== Phase 2: stable rank sort ========================
    {
        float* s_keys = (float*)sraw;             // 2048
        int*   s_part = (int*)(sraw + 8192);      // 8 gaussians x 8 segs

        #pragma unroll
        for (int c = 0; c < 8; c++) {
            float4 k4 = ((const float4*)g_key)[c*64 + t];
            ((float4*)s_keys)[c*64 + t] = k4;
        }
        __syncthreads();

        int gi  = t >> 3;            // 0..7 gaussian within block
        int seg = t & 7;             // 0..7 key segment (256 keys)
        int i = b * 8 + gi;
        float ki = s_keys[i];
        int part = 0;
        const float4* k4 = (const float4*)s_keys + seg * 64;
        #pragma unroll 8
        for (int j4 = 0; j4 < 64; j4++) {
            float4 kk = k4[j4];
            int j = seg*256 + j4*4;
            part += (kk.x < ki) || (kk.x == ki && (j+0) < i);
            part += (kk.y < ki) || (kk.y == ki && (j+1) < i);
            part += (kk.z < ki) || (kk.z == ki && (j+2) < i);
            part += (kk.w < ki) || (kk.w == ki && (j+3) < i);
        }
        s_part[gi*8 + seg] = part;
        __syncthreads();

        if (t < 8) {
            int i2 = b * 8 + t;
            int rank = 0;
            #pragma unroll
            for (int s = 0; s < 8; s++) rank += s_part[t*8 + s];
            g_s0[rank]  = g_u0[i2];
            g_s1[rank]  = g_u1[i2];
            g_sb[rank]  = g_ub[i2];
            g_sbb[rank] = g_ubb[i2];
        }
    }

    grid_barrier();

    // ===================== Phase 3: 8x8-tile raster =========================
    {
        unsigned short* s_list = (unsigned short*)sraw;      // 2048
        int*    s_cnt = (int*)(sraw + 4096);                 // 32 chunks x 2 warps
        float4* sc0   = (float4*)(sraw + 4352);              // 64
        float4* sc1   = (float4*)(sraw + 5376);              // 64
        float*  scb   = (float*)(sraw + 6400);               // 64

        int tx = b & (TILES_X - 1);
        int ty = b >> 4;

        float ulo = ((float)(tx * TILE) + 0.5f - 64.0f) * 0.01f;
        float uhi = ulo + 7.0f * 0.01f;
        float vlo = ((float)(ty * TILE) + 0.5f - 64.0f) * 0.01f;
        float vhi = vlo + 7.0f * 0.01f;

        // --- Phase A pass 1: keep bits + per-(chunk,warp) counts ---
        unsigned keepbits = 0;
        #pragma unroll 4
        for (int c = 0; c < 32; c++) {
            int g = c * 64 + t;
            float4 p0 = g_s0[g];
            float2 bb = g_sbb[g];
            bool keep = (p0.x + bb.x >= ulo) && (p0.x - bb.x <= uhi) &&
                        (p0.y + bb.y >= vlo) && (p0.y - bb.y <= vhi);
            unsigned m = __ballot_sync(0xffffffffu, keep);
            keepbits |= ((unsigned)keep) << c;
            if (lane == 0) s_cnt[c*2 + wid] = __popc(m);
        }
        __syncthreads();

        // --- Phase A pass 2: ordered scatter via running prefix ---
        unsigned lmask = (1u << lane) - 1u;
        int run = 0;
        #pragma unroll 4
        for (int c = 0; c < 32; c++) {
            unsigned m = __ballot_sync(0xffffffffu, (keepbits >> c) & 1u);
            int c0 = s_cnt[c*2], c1 = s_cnt[c*2 + 1];
            if ((keepbits >> c) & 1u) {
                int off = run + (wid ? c0 : 0) + __popc(m & lmask);
                s_list[off] = (unsigned short)(c * 64 + t);
            }
            run += c0 + c1;
        }
        int L = run;
        __syncthreads();

        // --- Phase B: composite in depth order, staged 64-at-a-time ---
        int pi = ty * TILE + (t >> 3);
        int pj = tx * TILE + (t & 7);
        float pu = ((float)pj + 0.5f - 64.0f) * 0.01f;
        float pv = ((float)pi + 0.5f - 64.0f) * 0.01f;

        float T = 1.0f, cr = 0.0f, cg = 0.0f, cb = 0.0f;

        for (int base = 0; base < L; base += 64) {
            int n = min(64, L - base);
            if (t < n) {
                int g = s_list[base + t];
                sc0[t] = g_s0[g];
                sc1[t] = g_s1[g];
                scb[t] = g_sb[g];
            }
            __syncthreads();

            #pragma unroll 4
            for (int j = 0; j < n; j++) {
                float4 p0 = sc0[j];          // u, v, A2, B2
                float4 p1 = sc1[j];          // C2, lop, r, g
                float  bb = scb[j];
                float dx = pu - p0.x;
                float dy = pv - p0.y;
                float t4 = fmaf(p1.x, dy*dy, p1.y);                   // C2 dy^2 + lop
                float pw = fmaf(dx, fmaf(p0.z, dx, p0.w*dy), t4);     // + A2 dx^2 + B2 dx dy
                pw = fminf(pw, p1.y);        // == min(raw,0)+lop
                float alpha = fex2(pw);      // opa*exp(min(power,0)); <=0.9 so no clamp
                float w = T * alpha;
                cr = fmaf(w, p1.z, cr);
                cg = fmaf(w, p1.w, cg);
                cb = fmaf(w, bb, cb);
                T -= w;
            }
            if (__syncthreads_and(T < 1e-7f)) break;   // also the barrier for re-staging
        }

        int pix = pi * IMG + pj;
        out[3*pix + 0] = cr;
        out[3*pix + 1] = cg;
        out[3*pix + 2] = cb;
    }
}

// ---------------------------------------------------------------------------
extern "C" void kernel_launch(void* const* d_in, const int* in_sizes, int n_in,
                              void* d_out, int out_size) {
    const float* pos   = (const float*)d_in[0];
    const float* rgb   = (const float*)d_in[1];
    const float* opa   = (const float*)d_in[2];
    const float* quat  = (const float*)d_in[3];
    const float* scale = (const float*)d_in[4];
    const float* wq    = (const float*)d_in[5];
    const float* wt    = (const float*)d_in[6];
    float* out = (float*)d_out;

    k_fused<<<NBLK, TPB>>>(pos, rgb, opa, quat, scale, wq, wt, out);
}